// round 17
// baseline (speedup 1.0000x reference)
#include <cuda_runtime.h>
#include <cstdint>

// Problem constants
#define FE_    1024
#define FE4_   256            // FE in float4
#define T_     2048
#define B_     4
#define NCH_   32             // chunks over T for the x-sum (R7-proven)
#define TPC_   (T_ / NCH_)    // 64 timesteps per chunk
#define GA_    192            // merged kernel grid (128 x-sum + 64 cond)
#define EPS_   1e-5f

// Scratch (device globals — allocation is forbidden)
__device__ float4 g_part4[B_ * NCH_ * FE4_];   // x partial sums (0.5 MB)
__device__ float  g_ccraw[2 * FE_];            // raw Wc@c per branch
__device__ float4 g_cc4[2 * FE4_];             // LayerNormed cond vectors (v, o)
__device__ float4 g_sum4[B_ * FE4_];           // sum_t x
__device__ float4 g_d04[B_ * FE4_];            // raw v-matvec dots
__device__ float4 g_z4[B_ * FE4_];             // final per-batch rows

// Grid barrier state (zero-init; count self-resets each use -> replay safe)
__device__ int g_bar_count[3];
__device__ int g_bar_gen[3];

__device__ __forceinline__ void grid_barrier(int i)
{
    __syncthreads();
    if (threadIdx.x == 0) {
        volatile int* genp = &g_bar_gen[i];
        __threadfence();
        int my = *genp;
        if (atomicAdd(&g_bar_count[i], 1) == GA_ - 1) {
            g_bar_count[i] = 0;
            __threadfence();
            atomicExch(&g_bar_gen[i], my + 1);
        } else {
            while (*genp == my) __nanosleep(32);
        }
        __threadfence();
    }
    __syncthreads();
}

// ---------------------------------------------------------------------------
// KA (merged k1+k2, persistent over 192 blocks — R16 exact):
//   Phase 1: blocks [0,128): partial x-sum.  blocks [128,192): cond GEMV.
//   Phase A: blocks [0,128): chunk reduce -> g_sum; blocks 128,129: LN -> g_cc.
//   Phase B: blocks [0,128): v-matvec (8 rows/block, warp per row) -> g_d0.
//   Phase C: blocks [0,128): o-matvec -> g_z (bias folded in).
// ---------------------------------------------------------------------------
__global__ void __launch_bounds__(256, 2)
kA_fused(const float4* __restrict__ x4,
         const float*  __restrict__ c,
         const float4* __restrict__ vWc4, const float4* __restrict__ oWc4,
         const float*  __restrict__ vg,   const float*  __restrict__ vb,
         const float*  __restrict__ og,   const float*  __restrict__ ob,
         const float4* __restrict__ vWl4, const float4* __restrict__ vbl4,
         const float4* __restrict__ oWl4, const float*  __restrict__ obl)
{
    __shared__ float4 sh_m4[B_ * FE4_];    // 16 KB staging (reused per phase)
    __shared__ float  sh_s[256], sh_q[256];

    const int bid  = blockIdx.x;           // 0..191
    const int tid  = threadIdx.x;          // 0..255
    const int lane = tid & 31;
    const int warp = tid >> 5;             // 0..7

    // ================= Phase 1 =================
    if (bid < B_ * NCH_) {
        const int b  = bid >> 5;          // / NCH_
        const int ch = bid & 31;          // % NCH_
        const float4* p = x4 + (size_t)b * (T_ * FE4_)
                             + (size_t)ch * (TPC_ * FE4_) + tid;
        float4 a0 = make_float4(0.f, 0.f, 0.f, 0.f);
        float4 a1 = make_float4(0.f, 0.f, 0.f, 0.f);
        #pragma unroll 8
        for (int t = 0; t < TPC_; t += 2) {
            float4 u = p[(size_t)t * FE4_];
            float4 v = p[(size_t)(t + 1) * FE4_];
            a0.x += u.x; a0.y += u.y; a0.z += u.z; a0.w += u.w;
            a1.x += v.x; a1.y += v.y; a1.z += v.z; a1.w += v.w;
        }
        g_part4[(size_t)bid * FE4_ + tid] =
            make_float4(a0.x + a1.x, a0.y + a1.y, a0.z + a1.z, a0.w + a1.w);
    } else {
        const int idx    = bid - B_ * NCH_;   // 0..63
        const int branch = idx >> 5;          // 0=v, 1=o
        const int rblk   = idx & 31;
        const float4* Wc4 = (branch == 0) ? vWc4 : oWc4;

        float4* s_c4 = sh_m4;                 // reuse staging for c_flat
        if (tid < 64) s_c4[tid] = reinterpret_cast<const float4*>(c)[tid];
        __syncthreads();

        float* outp = g_ccraw + branch * FE_;
        #pragma unroll
        for (int rr = 0; rr < 4; rr++) {
            const int row = rblk * 32 + warp * 4 + rr;
            const float4* wr = Wc4 + (size_t)row * 64;
            float4 w0 = wr[lane], w1 = wr[lane + 32];
            float4 c0 = s_c4[lane], c1 = s_c4[lane + 32];
            float acc = w0.x*c0.x + w0.y*c0.y + w0.z*c0.z + w0.w*c0.w
                      + w1.x*c1.x + w1.y*c1.y + w1.z*c1.z + w1.w*c1.w;
            #pragma unroll
            for (int off = 16; off; off >>= 1)
                acc += __shfl_down_sync(0xffffffffu, acc, off);
            if (lane == 0) outp[row] = acc;
        }
    }
    grid_barrier(0);

    // ================= Phase A =================
    if (bid < 128) {
        const int b   = bid >> 5;
        const int col = (bid & 31) * 8 + warp;
        float4 a = g_part4[(size_t)(b * NCH_ + lane) * FE4_ + col];
        #pragma unroll
        for (int off = 16; off; off >>= 1) {
            a.x += __shfl_down_sync(0xffffffffu, a.x, off);
            a.y += __shfl_down_sync(0xffffffffu, a.y, off);
            a.z += __shfl_down_sync(0xffffffffu, a.z, off);
            a.w += __shfl_down_sync(0xffffffffu, a.w, off);
        }
        if (lane == 0) g_sum4[b * FE4_ + col] = a;
    } else if (bid < 130) {
        const int br = bid - 128;
        const float* raw = g_ccraw + br * FE_;
        float v0 = raw[tid], v1 = raw[tid + 256], v2 = raw[tid + 512], v3 = raw[tid + 768];
        sh_s[tid] = v0 + v1 + v2 + v3;
        sh_q[tid] = v0*v0 + v1*v1 + v2*v2 + v3*v3;
        __syncthreads();
        for (int off = 128; off; off >>= 1) {
            if (tid < off) { sh_s[tid] += sh_s[tid + off]; sh_q[tid] += sh_q[tid + off]; }
            __syncthreads();
        }
        const float mu   = sh_s[0] * (1.0f / FE_);
        const float var  = sh_q[0] * (1.0f / FE_) - mu * mu;
        const float rstd = rsqrtf(var + EPS_);
        const float* gg  = br ? og : vg;
        const float* bb  = br ? ob : vb;
        float* cc = reinterpret_cast<float*>(g_cc4) + br * FE_;
        cc[tid      ] = (v0 - mu) * rstd * gg[tid      ] + bb[tid      ];
        cc[tid + 256] = (v1 - mu) * rstd * gg[tid + 256] + bb[tid + 256];
        cc[tid + 512] = (v2 - mu) * rstd * gg[tid + 512] + bb[tid + 512];
        cc[tid + 768] = (v3 - mu) * rstd * gg[tid + 768] + bb[tid + 768];
    }
    grid_barrier(1);

    // ================= Phase B: v-matvec =================
    if (bid < 128) {
        #pragma unroll
        for (int k = 0; k < 4; k++) {
            const int idx = tid + k * 256;
            float4 s = g_sum4[idx], cv = g_cc4[tid];
            sh_m4[idx] = make_float4(s.x*cv.x, s.y*cv.y, s.z*cv.z, s.w*cv.w);
        }
        __syncthreads();

        const int row = bid * 8 + warp;
        const float4* wr = vWl4 + (size_t)row * FE4_;
        float4 W0 = wr[lane      ], W1 = wr[lane +  32];
        float4 W2 = wr[lane +  64], W3 = wr[lane +  96];
        float4 W4 = wr[lane + 128], W5 = wr[lane + 160];
        float4 W6 = wr[lane + 192], W7 = wr[lane + 224];
        float4 Wk[8] = {W0, W1, W2, W3, W4, W5, W6, W7};
        float a0=0.f, a1=0.f, a2=0.f, a3=0.f;
        #pragma unroll
        for (int k = 0; k < 8; k++) {
            const int j = lane + k * 32;
            float4 w = Wk[k];
            float4 m0 = sh_m4[j], m1 = sh_m4[j+256], m2 = sh_m4[j+512], m3 = sh_m4[j+768];
            a0 += w.x*m0.x + w.y*m0.y + w.z*m0.z + w.w*m0.w;
            a1 += w.x*m1.x + w.y*m1.y + w.z*m1.z + w.w*m1.w;
            a2 += w.x*m2.x + w.y*m2.y + w.z*m2.z + w.w*m2.w;
            a3 += w.x*m3.x + w.y*m3.y + w.z*m3.z + w.w*m3.w;
        }
        #pragma unroll
        for (int off = 16; off; off >>= 1) {
            a0 += __shfl_down_sync(0xffffffffu, a0, off);
            a1 += __shfl_down_sync(0xffffffffu, a1, off);
            a2 += __shfl_down_sync(0xffffffffu, a2, off);
            a3 += __shfl_down_sync(0xffffffffu, a3, off);
        }
        if (lane == 0) {
            float* d0 = reinterpret_cast<float*>(g_d04);
            d0[0 * FE_ + row] = a0;
            d0[1 * FE_ + row] = a1;
            d0[2 * FE_ + row] = a2;
            d0[3 * FE_ + row] = a3;
        }
    }
    grid_barrier(2);

    // ================= Phase C: o-matvec =================
    if (bid < 128) {
        const float Tf = (float)T_;
        #pragma unroll
        for (int k = 0; k < 4; k++) {
            const int idx = tid + k * 256;
            float4 d = g_d04[idx], cv = g_cc4[FE4_ + tid], bl = vbl4[tid];
            sh_m4[idx] = make_float4((d.x + Tf*bl.x)*cv.x, (d.y + Tf*bl.y)*cv.y,
                                     (d.z + Tf*bl.z)*cv.z, (d.w + Tf*bl.w)*cv.w);
        }
        __syncthreads();

        const int row = bid * 8 + warp;
        const float4* wr = oWl4 + (size_t)row * FE4_;
        float4 W0 = wr[lane      ], W1 = wr[lane +  32];
        float4 W2 = wr[lane +  64], W3 = wr[lane +  96];
        float4 W4 = wr[lane + 128], W5 = wr[lane + 160];
        float4 W6 = wr[lane + 192], W7 = wr[lane + 224];
        float4 Wk[8] = {W0, W1, W2, W3, W4, W5, W6, W7};
        float a0=0.f, a1=0.f, a2=0.f, a3=0.f;
        #pragma unroll
        for (int k = 0; k < 8; k++) {
            const int j = lane + k * 32;
            float4 w = Wk[k];
            float4 m0 = sh_m4[j], m1 = sh_m4[j+256], m2 = sh_m4[j+512], m3 = sh_m4[j+768];
            a0 += w.x*m0.x + w.y*m0.y + w.z*m0.z + w.w*m0.w;
            a1 += w.x*m1.x + w.y*m1.y + w.z*m1.z + w.w*m1.w;
            a2 += w.x*m2.x + w.y*m2.y + w.z*m2.z + w.w*m2.w;
            a3 += w.x*m3.x + w.y*m3.y + w.z*m3.z + w.w*m3.w;
        }
        #pragma unroll
        for (int off = 16; off; off >>= 1) {
            a0 += __shfl_down_sync(0xffffffffu, a0, off);
            a1 += __shfl_down_sync(0xffffffffu, a1, off);
            a2 += __shfl_down_sync(0xffffffffu, a2, off);
            a3 += __shfl_down_sync(0xffffffffu, a3, off);
        }
        if (lane == 0) {
            const float bs = obl[row];
            float* z = reinterpret_cast<float*>(g_z4);
            z[0 * FE_ + row] = a0 + bs;
            z[1 * FE_ + row] = a1 + bs;
            z[2 * FE_ + row] = a2 + bs;
            z[3 * FE_ + row] = a3 + bs;
        }
    }
}

// ---------------------------------------------------------------------------
// K3: broadcast z[b] over T — TMA bulk-store path.
// Each block stages its 16-timestep (16 KB contiguous) output span in smem,
// then one thread issues a single cp.async.bulk to global. This rides the
// TMA/LTS path (~6300 B/cyc chip cap, path-independent per B300 measurements)
// instead of the STG path that plateaued at ~2100 B/cyc.
// ---------------------------------------------------------------------------
__global__ void __launch_bounds__(256)
bcast_kernel(float4* __restrict__ out4)
{
    __shared__ float4 sbuf[16 * FE4_ / 16];    // 16 t * 256 f4 = 16 KB... see below
    // NOTE: 16 timesteps * 256 float4 = 4096 float4 = 64 KB would exceed smem;
    // actual span staged: 16 timesteps of 1 KB = 16 KB = 1024 float4.
    // sbuf dimensioned accordingly:
    // (16 * FE4_ / 16) wrong on purpose? No: FE row = 256 float4 = 4 KB? No —
    // FE_=1024 floats = 4 KB per timestep. 16 timesteps = 64 KB. Too big.
    // => stage 4 timesteps (16 KB) and issue 4 bulk copies of 4 KB... see code.
    const int bid = blockIdx.x;            // 0..511
    const int tid = threadIdx.x;           // 0..255
    const int b   = bid >> 7;
    const int tg  = bid & 127;

    const float4 zv = g_z4[b * FE4_ + tid];
    // Stage ONE 4 KB row (the repeated unit) in smem.
    sbuf[tid] = zv;
    __syncthreads();
    asm volatile("fence.proxy.async.shared::cta;" ::: "memory");

    // Issue 16 bulk copies of the 4 KB row, one per timestep (contiguous span).
    if (tid == 0) {
        uint32_t saddr;
        asm("{ .reg .u64 t; cvta.to.shared.u64 t, %1; cvt.u32.u64 %0, t; }"
            : "=r"(saddr) : "l"(sbuf));
        char* gbase = reinterpret_cast<char*>(
            out4 + (size_t)b * (T_ * FE4_) + (size_t)tg * (16 * FE4_));
        #pragma unroll
        for (int t = 0; t < 16; t++) {
            asm volatile(
                "cp.async.bulk.global.shared::cta.bulk_group [%0], [%1], %2;"
                :: "l"(gbase + (size_t)t * 4096), "r"(saddr), "n"(4096)
                : "memory");
        }
        asm volatile("cp.async.bulk.commit_group;" ::: "memory");
        asm volatile("cp.async.bulk.wait_group 0;" ::: "memory");
    }
    __syncthreads();
}

// ---------------------------------------------------------------------------
extern "C" void kernel_launch(void* const* d_in, const int* in_sizes, int n_in,
                              void* d_out, int out_size)
{
    const float* x   = (const float*)d_in[0];
    const float* c   = (const float*)d_in[1];
    // q (3-7), k (8-12) branches and C (2) cancel analytically:
    //   y[b,t] = sum_u v[b,u]  because sum_q softmax(...) == 1 and the final
    //   einsum 'bftq,bufe->btfe' sums both q and u independently.
    const float* vWl = (const float*)d_in[13];
    const float* vbl = (const float*)d_in[14];
    const float* vWc = (const float*)d_in[15];
    const float* vg  = (const float*)d_in[16];
    const float* vb  = (const float*)d_in[17];
    const float* oWl = (const float*)d_in[18];
    const float* obl = (const float*)d_in[19];
    const float* oWc = (const float*)d_in[20];
    const float* og  = (const float*)d_in[21];
    const float* ob  = (const float*)d_in[22];

    kA_fused<<<GA_, 256>>>((const float4*)x, c,
                           (const float4*)vWc, (const float4*)oWc,
                           vg, vb, og, ob,
                           (const float4*)vWl, (const float4*)vbl,
                           (const float4*)oWl, obl);
    bcast_kernel<<<B_ * T_ / 16, 256>>>((float4*)d_out);
}